// round 8
// baseline (speedup 1.0000x reference)
#include <cuda_runtime.h>
#include <cuda_bf16.h>
#include <cstdint>
#include <math.h>

#define L 8192
#define K 48
#define SENTK 0xFFFFFFFFFFFFFFFFULL
typedef unsigned long long ull;

// ---------------- device scratch (static; allocation-free) ----------------
__device__ __align__(16) float g_A[L * 128];
__device__ __align__(16) float g_B[L * 128];
__device__ __align__(16) ull   g_Wsm2P[16 * 128];      // [q2][c] = (We[c][128+2q2], We[c][128+2q2+1])
__device__ __align__(16) float g_WAT[128 * 128];
__device__ __align__(16) float g_WfT[128 * 128];
__device__ __align__(16) float g_WhT[128 * 128];
__device__ __align__(16) float g_w1[128];
__device__ __align__(16) float g_c0[128];
__device__ __align__(16) __nv_bfloat16 g_WT_hi[128 * 128]; // [n][c] bf16 hi of Wproj[n][c]*ln_scale[c]
__device__ __align__(16) __nv_bfloat16 g_WT_lo[128 * 128]; // residual
__device__ int   g_knn_idx[L * K];
__device__ float g_knn_d[L * K];

// ---------------- helpers ----------------
__device__ __forceinline__ ull fma2(ull a, ull b, ull c) {
    ull d;
    asm("fma.rn.f32x2 %0, %1, %2, %3;" : "=l"(d) : "l"(a), "l"(b), "l"(c));
    return d;
}
__device__ __forceinline__ ull pack2(float lo, float hi) {
    ull d;
    asm("mov.b64 %0, {%1, %2};" : "=l"(d) : "r"(__float_as_uint(lo)), "r"(__float_as_uint(hi)));
    return d;
}
__device__ __forceinline__ float lo2(ull v) { return __uint_as_float((unsigned)v); }
__device__ __forceinline__ float hi2(ull v) { return __uint_as_float((unsigned)(v >> 32)); }

__device__ __forceinline__ uint32_t smem_u32(const void* p) {
    uint32_t a;
    asm("{ .reg .u64 t; cvta.to.shared.u64 t, %1; cvt.u32.u64 %0, t; }" : "=r"(a) : "l"(p));
    return a;
}
__device__ __forceinline__ void ldm4(uint32_t* r, uint32_t addr) {
    asm volatile("ldmatrix.sync.aligned.m8n8.x4.shared.b16 {%0,%1,%2,%3}, [%4];"
                 : "=r"(r[0]), "=r"(r[1]), "=r"(r[2]), "=r"(r[3]) : "r"(addr));
}
__device__ __forceinline__ void mma_bf16(float* c, const uint32_t* a, const uint32_t* b) {
    asm volatile("mma.sync.aligned.m16n8k16.row.col.f32.bf16.bf16.f32 "
                 "{%0,%1,%2,%3}, {%4,%5,%6,%7}, {%8,%9}, {%0,%1,%2,%3};"
                 : "+f"(c[0]), "+f"(c[1]), "+f"(c[2]), "+f"(c[3])
                 : "r"(a[0]), "r"(a[1]), "r"(a[2]), "r"(a[3]), "r"(b[0]), "r"(b[1]));
}

// ---------------- tiny precompute ----------------
__global__ void prep_small_kernel(const float* __restrict__ Wproj,
                                  const float* __restrict__ ln_scale,
                                  const float* __restrict__ ln_bias,
                                  const float* __restrict__ bproj,
                                  const float* __restrict__ We) {
    int gid = blockIdx.x * blockDim.x + threadIdx.x;
    int NT = gridDim.x * blockDim.x;
    for (int n = gid; n < 16384; n += NT) {
        int c = n >> 7, t = n & 127;
        g_WAT[n] = We[t * 416 + 160 + c];
        g_WfT[n] = We[t * 416 + c];
        g_WhT[n] = We[t * 416 + 288 + c];
        int tt = n >> 7, cc = n & 127;
        float w = Wproj[tt * 128 + cc] * ln_scale[cc];
        __nv_bfloat16 h = __float2bfloat16(w);
        float res = w - __bfloat162float(h);
        g_WT_hi[n] = h;
        g_WT_lo[n] = __float2bfloat16(res);
    }
    for (int n = gid; n < 2048; n += NT) {
        int q2 = n >> 7, c = n & 127;
        g_Wsm2P[n] = pack2(We[c * 416 + 128 + 2 * q2], We[c * 416 + 128 + 2 * q2 + 1]);
    }
    if (gid < 128) {
        float s1 = 0.f, s0 = 0.f;
        for (int c = 0; c < 128; c++) {
            float w = Wproj[gid * 128 + c];
            s1 += w * ln_scale[c];
            s0 += w * ln_bias[c];
        }
        g_w1[gid] = s1;
        g_c0[gid] = s0 + bproj[gid];
    }
}

// ---------------- A/B tables ----------------
__global__ void __launch_bounds__(128) prep_ab_kernel(const float* __restrict__ node_h,
                                                      const float* __restrict__ f_node) {
    __shared__ float nh[32 * 128];
    __shared__ float fn[32 * 128];
    int tid = threadIdx.x;
    int i0 = blockIdx.x * 32;
    for (int f = tid; f < 32 * 128; f += 128) {
        nh[f] = node_h[i0 * 128 + f];
        fn[f] = f_node[i0 * 128 + f];
    }
    __syncthreads();
    for (int ch = 0; ch < 4; ch++) {
        float a[8], b[8];
#pragma unroll
        for (int ii = 0; ii < 8; ii++) { a[ii] = 0.f; b[ii] = 0.f; }
#pragma unroll 4
        for (int c = 0; c < 128; c++) {
            float wa = __ldg(g_WAT + c * 128 + tid);
            float wf = __ldg(g_WfT + c * 128 + tid);
            float wh = __ldg(g_WhT + c * 128 + tid);
#pragma unroll
            for (int ii = 0; ii < 8; ii++) {
                int row = ch * 8 + ii;
                float n = nh[row * 128 + c];
                float f = fn[row * 128 + c];
                a[ii] = fmaf(n, wa, a[ii]);
                b[ii] = fmaf(f, wf, fmaf(n, wh, b[ii]));
            }
        }
#pragma unroll
        for (int ii = 0; ii < 8; ii++) {
            g_A[(i0 + ch * 8 + ii) * 128 + tid] = a[ii];
            g_B[(i0 + ch * 8 + ii) * 128 + tid] = b[ii];
        }
    }
}

// ---------------- KNN (unchanged, passing) ----------------
__global__ void __launch_bounds__(512) knn_kernel(const float* __restrict__ X) {
    extern __shared__ float sx[];
    int tid = threadIdx.x;
    for (int idx = tid; idx < L; idx += 512) {
        sx[idx]         = X[3 * idx];
        sx[L + idx]     = X[3 * idx + 1];
        sx[2 * L + idx] = X[3 * idx + 2];
    }
    __syncthreads();
    int lane = tid & 31;
    int i = blockIdx.x * 16 + (tid >> 5);
    float xi = sx[i], yi = sx[L + i], zi = sx[2 * L + i];

    ull h[8];
#pragma unroll
    for (int m = 0; m < 8; m++) h[m] = SENTK;

#pragma unroll 4
    for (int s = 0; s < L / 32; s++) {
        int j = lane + (s << 5);
        float dx = xi - sx[j], dy = yi - sx[L + j], dz = zi - sx[2 * L + j];
        float ssq = __fadd_rn(__fadd_rn(__fmul_rn(dx, dx), __fmul_rn(dy, dy)), __fmul_rn(dz, dz));
        unsigned sb = __float_as_uint(ssq);
        unsigned hs = (unsigned)(h[7] >> 32);
        if (sb < hs || (sb == hs && (unsigned)j < (unsigned)h[7])) {
            h[7] = ((ull)sb << 32) | (unsigned)j;
#pragma unroll
            for (int m = 7; m > 0; m--)
                if (h[m] < h[m - 1]) { ull t = h[m]; h[m] = h[m - 1]; h[m - 1] = t; }
        }
    }

    ull mylast = 0ULL;
    for (int r = 0; r < K; r++) {
        if (h[0] == SENTK) {
            for (int s = 0; s < L / 32; s++) {
                int j = lane + (s << 5);
                float dx = xi - sx[j], dy = yi - sx[L + j], dz = zi - sx[2 * L + j];
                float ssq = __fadd_rn(__fadd_rn(__fmul_rn(dx, dx), __fmul_rn(dy, dy)), __fmul_rn(dz, dz));
                ull key = ((ull)__float_as_uint(ssq) << 32) | (unsigned)j;
                if (key > mylast && key < h[7]) {
                    h[7] = key;
#pragma unroll
                    for (int m = 7; m > 0; m--)
                        if (h[m] < h[m - 1]) { ull t = h[m]; h[m] = h[m - 1]; h[m - 1] = t; }
                }
            }
        }
        ull mn = h[0];
#pragma unroll
        for (int off = 16; off > 0; off >>= 1) {
            ull o = __shfl_xor_sync(0xffffffffu, mn, off);
            mn = (o < mn) ? o : mn;
        }
        if (h[0] == mn) {
            mylast = mn;
#pragma unroll
            for (int m = 0; m < 7; m++) h[m] = h[m + 1];
            h[7] = SENTK;
            g_knn_idx[i * K + r] = (int)(unsigned)(mn & 0xFFFFFFFFULL);
            float ssq = __uint_as_float((unsigned)(mn >> 32));
            g_knn_d[i * K + r] = sqrtf(ssq + 1e-6f);
        }
    }
}

// ---------------- fused: features + LN stats + 3-term bf16 mma projection ----------------
// smem byte offsets (total 103168)
#define SSTR 136
#define WHI_O 0
#define WLO_O 34816
#define EHI_O 69632
#define ELO_O 82688
#define SML_O 95744
#define SA_O  101888
#define MEAN_O 102400
#define RSTD_O 102592
#define SJ_O   102784
#define SD_O   102976
#define FUSED_SMEM 103168

__global__ void __launch_bounds__(256, 2) fused_kernel(const float* __restrict__ X,
                                                       const float* __restrict__ Wpos,
                                                       const float* __restrict__ bpos,
                                                       const int* __restrict__ aatype,
                                                       const int* __restrict__ resi,
                                                       float* __restrict__ out) {
    extern __shared__ __align__(16) char gsm[];
    uint32_t sb = smem_u32(gsm);
    float* sSmall = (float*)(gsm + SML_O);
    float* sA     = (float*)(gsm + SA_O);
    float* sMean  = (float*)(gsm + MEAN_O);
    float* sRstd  = (float*)(gsm + RSTD_O);
    int*   sJ     = (int*)(gsm + SJ_O);
    float* sD     = (float*)(gsm + SD_O);

    int tid = threadIdx.x;
    int wid = tid >> 5, lane = tid & 31;
    int i = blockIdx.x;

    // ---- stage W hi/lo (L2-resident) + per-row data ----
#pragma unroll
    for (int it = 0; it < 8; it++) {
        int vec = it * 256 + tid;           // uint4 = 8 bf16
        int n = vec >> 4;
        int c8 = (vec & 15) << 3;
        uint32_t so = (uint32_t)n * (SSTR * 2) + c8 * 2;
        *(uint4*)(gsm + WHI_O + so) = __ldg((const uint4*)(g_WT_hi + (size_t)n * 128 + c8));
        *(uint4*)(gsm + WLO_O + so) = __ldg((const uint4*)(g_WT_lo + (size_t)n * 128 + c8));
    }
    if (tid < 32) ((float4*)sA)[tid] = ((const float4*)(g_A + (size_t)i * 128))[tid];
    if (tid >= 64 && tid < 64 + K) {
        int k = tid - 64;
        sJ[k] = g_knn_idx[i * K + k];
        sD[k] = g_knn_d[i * K + k];
    }
    __syncthreads();

    // ---- Phase A: per-edge small features (48 threads) ----
    if (tid < K) {
        int k = tid;
        int j = sJ[k];
        float d = sD[k];
        float rb[16];
#pragma unroll
        for (int q = 0; q < 16; q++) {
            float mu = 2.0f + (20.0f / 15.0f) * (float)q;
            float t = (d - mu) * 0.8f;
            rb[q] = expf(-t * t);
            sSmall[k * 32 + 16 + q] = rb[q];
        }
        float gm[8];
        gm[0] = d * 0.1f;
        gm[1] = 1.0f / (1.0f + d);
        gm[2] = expf(-d);
        gm[3] = sinf(d);
        gm[4] = cosf(d);
        float inv = 1.0f / (d + 1e-6f);
        float xs = X[3 * i], ys = X[3 * i + 1], zs = X[3 * i + 2];
        gm[5] = (X[3 * j] - xs) * inv;
        gm[6] = (X[3 * j + 1] - ys) * inv;
        gm[7] = (X[3 * j + 2] - zs) * inv;
        int off = resi[j] - resi[i];
        int p = min(max(off + 8, 0), 15);
        int aa = aatype[j];
#pragma unroll
        for (int r = 0; r < 16; r++) {
            const float* wr = Wpos + r * 66;
            float acc = bpos[r] + __ldg(wr + p) + __ldg(wr + 40 + aa);
#pragma unroll
            for (int q = 0; q < 16; q++) acc = fmaf(rb[q], __ldg(wr + 16 + q), acc);
#pragma unroll
            for (int g = 0; g < 8; g++) acc = fmaf(gm[g], __ldg(wr + 32 + g), acc);
            sSmall[k * 32 + r] = acc;
        }
    }
    __syncthreads();

    // ---- Phase B: e[k][c] = A[c] + B[j_k][c] + small[k,:].w[:,c]; split bf16 hi/lo ----
    {
        int c = tid & 127;
        int kh = tid >> 7;                 // 0 or 1 -> k in [kh*24, kh*24+24)
        ull w2[16];
#pragma unroll
        for (int q2 = 0; q2 < 16; q2++) w2[q2] = __ldg(g_Wsm2P + q2 * 128 + c);
        float a = sA[c];
        int k0 = kh * 24;
#pragma unroll 4
        for (int kk = 0; kk < 24; kk++) {
            int k = k0 + kk;
            ull acc = pack2(a + __ldg(g_B + (size_t)sJ[k] * 128 + c), 0.f);
            const ull* s2 = (const ull*)(sSmall + k * 32);
#pragma unroll
            for (int q2 = 0; q2 < 16; q2++) acc = fma2(s2[q2], w2[q2], acc);
            float e = lo2(acc) + hi2(acc);
            __nv_bfloat16 h = __float2bfloat16(e);
            __nv_bfloat16 l = __float2bfloat16(e - __bfloat162float(h));
            uint32_t so = (uint32_t)k * (SSTR * 2) + c * 2;
            *(__nv_bfloat16*)(gsm + EHI_O + so) = h;
            *(__nv_bfloat16*)(gsm + ELO_O + so) = l;
        }
    }
    __syncthreads();

    // ---- LN stats from hi+lo (per-k over 128 c) ----
    {
        for (int k = wid; k < K; k += 8) {
            float s = 0.f, ss = 0.f;
#pragma unroll
            for (int q = 0; q < 4; q++) {
                int c = lane + q * 32;
                uint32_t so = (uint32_t)k * (SSTR * 2) + c * 2;
                float v = __bfloat162float(*(__nv_bfloat16*)(gsm + EHI_O + so)) +
                          __bfloat162float(*(__nv_bfloat16*)(gsm + ELO_O + so));
                s += v;
                ss = fmaf(v, v, ss);
            }
#pragma unroll
            for (int off = 16; off > 0; off >>= 1) {
                s += __shfl_xor_sync(0xffffffffu, s, off);
                ss += __shfl_xor_sync(0xffffffffu, ss, off);
            }
            if (lane == 0) {
                float mean = s * (1.0f / 128.0f);
                float var = ss * (1.0f / 128.0f) - mean * mean;
                sMean[k] = mean;
                sRstd[k] = rsqrtf(var + 1e-5f);
            }
        }
    }
    __syncthreads();

    // ---- MMA: warp w handles n-slice [w*16, w*16+16), all 48 m-rows ----
    {
        int n_base = wid * 16;
        int g = lane >> 3, ri = lane & 7;

        uint32_t aoff[3];
#pragma unroll
        for (int mf = 0; mf < 3; mf++)
            aoff[mf] = (uint32_t)((mf * 16 + ri + (g & 1) * 8) * SSTR + (g >> 1) * 8) * 2;
        uint32_t boff = (uint32_t)((n_base + ri + (g >> 1) * 8) * SSTR + (g & 1) * 8) * 2;

        float acc[3][2][4];
#pragma unroll
        for (int mf = 0; mf < 3; mf++)
#pragma unroll
            for (int nf = 0; nf < 2; nf++)
#pragma unroll
                for (int q = 0; q < 4; q++) acc[mf][nf][q] = 0.f;

#pragma unroll
        for (int ks = 0; ks < 8; ks++) {
            uint32_t kb = ks * 32;
            uint32_t ah[3][4], al[3][4], bh[4], bl[4];
#pragma unroll
            for (int mf = 0; mf < 3; mf++) {
                ldm4(ah[mf], sb + EHI_O + aoff[mf] + kb);
                ldm4(al[mf], sb + ELO_O + aoff[mf] + kb);
            }
            ldm4(bh, sb + WHI_O + boff + kb);
            ldm4(bl, sb + WLO_O + boff + kb);
#pragma unroll
            for (int mf = 0; mf < 3; mf++) {
#pragma unroll
                for (int nf = 0; nf < 2; nf++) {
                    const uint32_t* bhp = &bh[nf * 2];
                    const uint32_t* blp = &bl[nf * 2];
                    mma_bf16(acc[mf][nf], ah[mf], bhp);
                    mma_bf16(acc[mf][nf], ah[mf], blp);
                    mma_bf16(acc[mf][nf], al[mf], bhp);
                }
            }
        }

        // ---- epilogue: LN fold + store ----
#pragma unroll
        for (int mf = 0; mf < 3; mf++) {
            int r0 = mf * 16 + (lane >> 2);
            float mean0 = sMean[r0], rstd0 = sRstd[r0];
            float mean1 = sMean[r0 + 8], rstd1 = sRstd[r0 + 8];
#pragma unroll
            for (int nf = 0; nf < 2; nf++) {
                int col = n_base + nf * 8 + (lane & 3) * 2;
                float2 w1v = *(const float2*)(g_w1 + col);
                float2 c0v = *(const float2*)(g_c0 + col);
                float2 o0, o1;
                o0.x = fmaf(rstd0, acc[mf][nf][0] - mean0 * w1v.x, c0v.x);
                o0.y = fmaf(rstd0, acc[mf][nf][1] - mean0 * w1v.y, c0v.y);
                o1.x = fmaf(rstd1, acc[mf][nf][2] - mean1 * w1v.x, c0v.x);
                o1.y = fmaf(rstd1, acc[mf][nf][3] - mean1 * w1v.y, c0v.y);
                *(float2*)(out + ((size_t)i * K + r0) * 128 + col) = o0;
                *(float2*)(out + ((size_t)i * K + r0 + 8) * 128 + col) = o1;
            }
        }
    }
}

// ---------------- launch ----------------
extern "C" void kernel_launch(void* const* d_in, const int* in_sizes, int n_in,
                              void* d_out, int out_size) {
    const float* X        = (const float*)d_in[0];
    const float* node_h   = (const float*)d_in[1];
    const float* f_node   = (const float*)d_in[2];
    const float* Wpos     = (const float*)d_in[3];
    const float* bpos     = (const float*)d_in[4];
    const float* We       = (const float*)d_in[5];
    const float* ln_scale = (const float*)d_in[6];
    const float* ln_bias  = (const float*)d_in[7];
    const float* Wproj    = (const float*)d_in[8];
    const float* bproj    = (const float*)d_in[9];
    const int*   aatype   = (const int*)d_in[10];
    const int*   resi     = (const int*)d_in[11];
    float* out = (float*)d_out;

    cudaFuncSetAttribute(knn_kernel, cudaFuncAttributeMaxDynamicSharedMemorySize, 3 * L * 4);
    cudaFuncSetAttribute(fused_kernel, cudaFuncAttributeMaxDynamicSharedMemorySize, FUSED_SMEM);

    prep_small_kernel<<<32, 256>>>(Wproj, ln_scale, ln_bias, bproj, We);
    prep_ab_kernel<<<L / 32, 128>>>(node_h, f_node);
    knn_kernel<<<L / 16, 512, 3 * L * 4>>>(X);
    fused_kernel<<<L, 256, FUSED_SMEM>>>(X, Wpos, bpos, aatype, resi, out);
}

// round 10
// speedup vs baseline: 1.1008x; 1.1008x over previous
#include <cuda_runtime.h>
#include <cuda_bf16.h>
#include <cstdint>
#include <math.h>

#define L 8192
#define K 48
#define SENTK 0xFFFFFFFFFFFFFFFFULL
typedef unsigned long long ull;

#define M_EDGES (L * K)          // 393216
#define N_TILES (M_EDGES / 128)  // 3072

// ---------------- device scratch (static; allocation-free) ----------------
__device__ __align__(16) float g_A[L * 128];
__device__ __align__(16) float g_B[L * 128];
__device__ __align__(16) ull   g_Wsm2P[16 * 128];      // [q2][c] packed pair of We[c][128+2q2(+1)]
__device__ __align__(16) float g_WAT[128 * 128];
__device__ __align__(16) float g_WfT[128 * 128];
__device__ __align__(16) float g_WhT[128 * 128];
__device__ __align__(16) float g_w1[128];
__device__ __align__(16) float g_c0[128];
__device__ __align__(16) __nv_bfloat16 g_WT_hi[128 * 128]; // [n][c] bf16 hi of Wproj[n][c]*ln_scale[c]
__device__ __align__(16) __nv_bfloat16 g_WT_lo[128 * 128]; // residual
__device__ int   g_knn_idx[L * K];
__device__ float g_knn_d[L * K];
__device__ __align__(16) __nv_bfloat16 g_Ehi[(size_t)M_EDGES * 128];
__device__ __align__(16) __nv_bfloat16 g_Elo[(size_t)M_EDGES * 128];
__device__ float g_mean[M_EDGES];
__device__ float g_rstd[M_EDGES];

// ---------------- helpers ----------------
__device__ __forceinline__ ull fma2(ull a, ull b, ull c) {
    ull d;
    asm("fma.rn.f32x2 %0, %1, %2, %3;" : "=l"(d) : "l"(a), "l"(b), "l"(c));
    return d;
}
__device__ __forceinline__ ull pack2(float lo, float hi) {
    ull d;
    asm("mov.b64 %0, {%1, %2};" : "=l"(d) : "r"(__float_as_uint(lo)), "r"(__float_as_uint(hi)));
    return d;
}
__device__ __forceinline__ float lo2(ull v) { return __uint_as_float((unsigned)v); }
__device__ __forceinline__ float hi2(ull v) { return __uint_as_float((unsigned)(v >> 32)); }

__device__ __forceinline__ uint32_t smem_u32(const void* p) {
    uint32_t a;
    asm("{ .reg .u64 t; cvta.to.shared.u64 t, %1; cvt.u32.u64 %0, t; }" : "=r"(a) : "l"(p));
    return a;
}
__device__ __forceinline__ void ldm4(uint32_t* r, uint32_t addr) {
    asm volatile("ldmatrix.sync.aligned.m8n8.x4.shared.b16 {%0,%1,%2,%3}, [%4];"
                 : "=r"(r[0]), "=r"(r[1]), "=r"(r[2]), "=r"(r[3]) : "r"(addr));
}
__device__ __forceinline__ void mma_bf16(float* c, const uint32_t* a, const uint32_t* b) {
    asm volatile("mma.sync.aligned.m16n8k16.row.col.f32.bf16.bf16.f32 "
                 "{%0,%1,%2,%3}, {%4,%5,%6,%7}, {%8,%9}, {%0,%1,%2,%3};"
                 : "+f"(c[0]), "+f"(c[1]), "+f"(c[2]), "+f"(c[3])
                 : "r"(a[0]), "r"(a[1]), "r"(a[2]), "r"(a[3]), "r"(b[0]), "r"(b[1]));
}

// ---------------- tiny precompute ----------------
__global__ void prep_small_kernel(const float* __restrict__ Wproj,
                                  const float* __restrict__ ln_scale,
                                  const float* __restrict__ ln_bias,
                                  const float* __restrict__ bproj,
                                  const float* __restrict__ We) {
    int gid = blockIdx.x * blockDim.x + threadIdx.x;
    int NT = gridDim.x * blockDim.x;
    for (int n = gid; n < 16384; n += NT) {
        int c = n >> 7, t = n & 127;
        g_WAT[n] = We[t * 416 + 160 + c];
        g_WfT[n] = We[t * 416 + c];
        g_WhT[n] = We[t * 416 + 288 + c];
        int tt = n >> 7, cc = n & 127;
        float w = Wproj[tt * 128 + cc] * ln_scale[cc];
        __nv_bfloat16 h = __float2bfloat16(w);
        float res = w - __bfloat162float(h);
        g_WT_hi[n] = h;
        g_WT_lo[n] = __float2bfloat16(res);
    }
    for (int n = gid; n < 2048; n += NT) {
        int q2 = n >> 7, c = n & 127;
        g_Wsm2P[n] = pack2(We[c * 416 + 128 + 2 * q2], We[c * 416 + 128 + 2 * q2 + 1]);
    }
    if (gid < 128) {
        float s1 = 0.f, s0 = 0.f;
        for (int c = 0; c < 128; c++) {
            float w = Wproj[gid * 128 + c];
            s1 += w * ln_scale[c];
            s0 += w * ln_bias[c];
        }
        g_w1[gid] = s1;
        g_c0[gid] = s0 + bproj[gid];
    }
}

// ---------------- A/B tables ----------------
__global__ void __launch_bounds__(128) prep_ab_kernel(const float* __restrict__ node_h,
                                                      const float* __restrict__ f_node) {
    __shared__ float nh[32 * 128];
    __shared__ float fn[32 * 128];
    int tid = threadIdx.x;
    int i0 = blockIdx.x * 32;
    for (int f = tid; f < 32 * 128; f += 128) {
        nh[f] = node_h[i0 * 128 + f];
        fn[f] = f_node[i0 * 128 + f];
    }
    __syncthreads();
    for (int ch = 0; ch < 4; ch++) {
        float a[8], b[8];
#pragma unroll
        for (int ii = 0; ii < 8; ii++) { a[ii] = 0.f; b[ii] = 0.f; }
#pragma unroll 4
        for (int c = 0; c < 128; c++) {
            float wa = __ldg(g_WAT + c * 128 + tid);
            float wf = __ldg(g_WfT + c * 128 + tid);
            float wh = __ldg(g_WhT + c * 128 + tid);
#pragma unroll
            for (int ii = 0; ii < 8; ii++) {
                int row = ch * 8 + ii;
                float n = nh[row * 128 + c];
                float f = fn[row * 128 + c];
                a[ii] = fmaf(n, wa, a[ii]);
                b[ii] = fmaf(f, wf, fmaf(n, wh, b[ii]));
            }
        }
#pragma unroll
        for (int ii = 0; ii < 8; ii++) {
            g_A[(i0 + ch * 8 + ii) * 128 + tid] = a[ii];
            g_B[(i0 + ch * 8 + ii) * 128 + tid] = b[ii];
        }
    }
}

// ---------------- KNN (unchanged, passing) ----------------
__global__ void __launch_bounds__(512) knn_kernel(const float* __restrict__ X) {
    extern __shared__ float sx[];
    int tid = threadIdx.x;
    for (int idx = tid; idx < L; idx += 512) {
        sx[idx]         = X[3 * idx];
        sx[L + idx]     = X[3 * idx + 1];
        sx[2 * L + idx] = X[3 * idx + 2];
    }
    __syncthreads();
    int lane = tid & 31;
    int i = blockIdx.x * 16 + (tid >> 5);
    float xi = sx[i], yi = sx[L + i], zi = sx[2 * L + i];

    ull h[8];
#pragma unroll
    for (int m = 0; m < 8; m++) h[m] = SENTK;

#pragma unroll 4
    for (int s = 0; s < L / 32; s++) {
        int j = lane + (s << 5);
        float dx = xi - sx[j], dy = yi - sx[L + j], dz = zi - sx[2 * L + j];
        float ssq = __fadd_rn(__fadd_rn(__fmul_rn(dx, dx), __fmul_rn(dy, dy)), __fmul_rn(dz, dz));
        unsigned sb = __float_as_uint(ssq);
        unsigned hs = (unsigned)(h[7] >> 32);
        if (sb < hs || (sb == hs && (unsigned)j < (unsigned)h[7])) {
            h[7] = ((ull)sb << 32) | (unsigned)j;
#pragma unroll
            for (int m = 7; m > 0; m--)
                if (h[m] < h[m - 1]) { ull t = h[m]; h[m] = h[m - 1]; h[m - 1] = t; }
        }
    }

    ull mylast = 0ULL;
    for (int r = 0; r < K; r++) {
        if (h[0] == SENTK) {
            for (int s = 0; s < L / 32; s++) {
                int j = lane + (s << 5);
                float dx = xi - sx[j], dy = yi - sx[L + j], dz = zi - sx[2 * L + j];
                float ssq = __fadd_rn(__fadd_rn(__fmul_rn(dx, dx), __fmul_rn(dy, dy)), __fmul_rn(dz, dz));
                ull key = ((ull)__float_as_uint(ssq) << 32) | (unsigned)j;
                if (key > mylast && key < h[7]) {
                    h[7] = key;
#pragma unroll
                    for (int m = 7; m > 0; m--)
                        if (h[m] < h[m - 1]) { ull t = h[m]; h[m] = h[m - 1]; h[m - 1] = t; }
                }
            }
        }
        ull mn = h[0];
#pragma unroll
        for (int off = 16; off > 0; off >>= 1) {
            ull o = __shfl_xor_sync(0xffffffffu, mn, off);
            mn = (o < mn) ? o : mn;
        }
        if (h[0] == mn) {
            mylast = mn;
#pragma unroll
            for (int m = 0; m < 7; m++) h[m] = h[m + 1];
            h[7] = SENTK;
            g_knn_idx[i * K + r] = (int)(unsigned)(mn & 0xFFFFFFFFULL);
            float ssq = __uint_as_float((unsigned)(mn >> 32));
            g_knn_d[i * K + r] = sqrtf(ssq + 1e-6f);
        }
    }
}

// ---------------- features: phases A+B + LN stats -> g_Ehi/g_Elo, g_mean, g_rstd ----------------
__global__ void __launch_bounds__(128, 4) features_kernel(const float* __restrict__ X,
                                                          const float* __restrict__ Wpos,
                                                          const float* __restrict__ bpos,
                                                          const int* __restrict__ aatype,
                                                          const int* __restrict__ resi) {
    extern __shared__ float sm[];
    float* sE     = sm;                // 48*132
    float* sSmall = sm + 6336;         // 48*32
    float* sA     = sm + 7872;         // 128
    int*   sJ     = (int*)(sm + 8000); // 48
    float* sD     = sm + 8048;         // 48

    int tid = threadIdx.x;
    int i = blockIdx.x;

    if (tid < 32) ((float4*)sA)[tid] = ((const float4*)(g_A + (size_t)i * 128))[tid];
    if (tid < K) { sJ[tid] = g_knn_idx[i * K + tid]; sD[tid] = g_knn_d[i * K + tid]; }
    __syncthreads();

    // Phase A
    if (tid < K) {
        int k = tid;
        int j = sJ[k];
        float d = sD[k];
        float rb[16];
#pragma unroll
        for (int q = 0; q < 16; q++) {
            float mu = 2.0f + (20.0f / 15.0f) * (float)q;
            float t = (d - mu) * 0.8f;
            rb[q] = expf(-t * t);
            sSmall[k * 32 + 16 + q] = rb[q];
        }
        float gm[8];
        gm[0] = d * 0.1f;
        gm[1] = 1.0f / (1.0f + d);
        gm[2] = expf(-d);
        gm[3] = sinf(d);
        gm[4] = cosf(d);
        float inv = 1.0f / (d + 1e-6f);
        float xs = X[3 * i], ys = X[3 * i + 1], zs = X[3 * i + 2];
        gm[5] = (X[3 * j] - xs) * inv;
        gm[6] = (X[3 * j + 1] - ys) * inv;
        gm[7] = (X[3 * j + 2] - zs) * inv;
        int off = resi[j] - resi[i];
        int p = min(max(off + 8, 0), 15);
        int aa = aatype[j];
#pragma unroll
        for (int r = 0; r < 16; r++) {
            const float* wr = Wpos + r * 66;
            float acc = bpos[r] + __ldg(wr + p) + __ldg(wr + 40 + aa);
#pragma unroll
            for (int q = 0; q < 16; q++) acc = fmaf(rb[q], __ldg(wr + 16 + q), acc);
#pragma unroll
            for (int g = 0; g < 8; g++) acc = fmaf(gm[g], __ldg(wr + 32 + g), acc);
            sSmall[k * 32 + r] = acc;
        }
    }
    __syncthreads();

    // Phase B: coalesced w2 loads; emit fp32 to sE and bf16 hi/lo to global
    {
        int c = tid;
        ull w2[16];
#pragma unroll
        for (int q2 = 0; q2 < 16; q2++) w2[q2] = __ldg(g_Wsm2P + q2 * 128 + c);
        float a = sA[c];
        size_t ebase = (size_t)i * K * 128;
        for (int k0 = 0; k0 < K; k0 += 4) {
            ull acc[4];
#pragma unroll
            for (int kk = 0; kk < 4; kk++)
                acc[kk] = pack2(a + __ldg(g_B + (size_t)sJ[k0 + kk] * 128 + c), 0.f);
#pragma unroll
            for (int q2 = 0; q2 < 16; q2++) {
#pragma unroll
                for (int kk = 0; kk < 4; kk++) {
                    ull s2 = *(const ull*)(sSmall + (k0 + kk) * 32 + q2 * 2);
                    acc[kk] = fma2(s2, w2[q2], acc[kk]);
                }
            }
#pragma unroll
            for (int kk = 0; kk < 4; kk++) {
                float e = lo2(acc[kk]) + hi2(acc[kk]);
                sE[(k0 + kk) * 132 + c] = e;
                __nv_bfloat16 h = __float2bfloat16(e);
                __nv_bfloat16 l = __float2bfloat16(e - __bfloat162float(h));
                g_Ehi[ebase + (size_t)(k0 + kk) * 128 + c] = h;
                g_Elo[ebase + (size_t)(k0 + kk) * 128 + c] = l;
            }
        }
    }
    __syncthreads();

    // LN stats (fp32)
    {
        int wrp = tid >> 5, lane = tid & 31;
        for (int k = wrp; k < K; k += 4) {
            float s = 0.f, ss = 0.f;
#pragma unroll
            for (int q = 0; q < 4; q++) {
                float v = sE[k * 132 + lane + q * 32];
                s += v;
                ss = fmaf(v, v, ss);
            }
#pragma unroll
            for (int off = 16; off > 0; off >>= 1) {
                s += __shfl_xor_sync(0xffffffffu, s, off);
                ss += __shfl_xor_sync(0xffffffffu, ss, off);
            }
            if (lane == 0) {
                float mean = s * (1.0f / 128.0f);
                float var = ss * (1.0f / 128.0f) - mean * mean;
                g_mean[i * K + k] = mean;
                g_rstd[i * K + k] = rsqrtf(var + 1e-5f);
            }
        }
    }
}

// ---------------- projection GEMM: mma.sync bf16 3-term split (R7-validated) ----------------
#define SSTR 136
#define EHI_OFF 0
#define ELO_OFF (128 * SSTR * 2)          // 34816
#define WHI_OFF (2 * 128 * SSTR * 2)      // 69632
#define WLO_OFF (3 * 128 * SSTR * 2)      // 104448
#define GEMM_SMEM (4 * 128 * SSTR * 2)    // 139264

__global__ void __launch_bounds__(256, 1) proj_gemm_kernel(float* __restrict__ out) {
    extern __shared__ __align__(16) char gsm[];
    uint32_t sb = smem_u32(gsm);
    int tid = threadIdx.x;
    int wid = tid >> 5, lane = tid & 31;
    int m0 = blockIdx.x * 128;

    // ---- stage W hi/lo ----
#pragma unroll
    for (int it = 0; it < 8; it++) {
        int vec = it * 256 + tid;           // uint4 = 8 bf16
        int n = vec >> 4;
        int c8 = (vec & 15) << 3;
        uint32_t so = (uint32_t)n * (SSTR * 2) + c8 * 2;
        *(uint4*)(gsm + WHI_OFF + so) = __ldg((const uint4*)(g_WT_hi + (size_t)n * 128 + c8));
        *(uint4*)(gsm + WLO_OFF + so) = __ldg((const uint4*)(g_WT_lo + (size_t)n * 128 + c8));
    }
    // ---- stage E hi/lo (pre-split; pure copies) ----
#pragma unroll
    for (int it = 0; it < 8; it++) {
        int vec = it * 256 + tid;           // uint4 = 8 bf16
        int r = vec >> 4;
        int c8 = (vec & 15) << 3;
        uint32_t so = (uint32_t)r * (SSTR * 2) + c8 * 2;
        *(uint4*)(gsm + EHI_OFF + so) = __ldg((const uint4*)(g_Ehi + ((size_t)(m0 + r) << 7) + c8));
        *(uint4*)(gsm + ELO_OFF + so) = __ldg((const uint4*)(g_Elo + ((size_t)(m0 + r) << 7) + c8));
    }
    __syncthreads();

    // ---- warp tiles: 2 m-groups x 4 n-groups; each warp 64m x 32n ----
    int m_base = (wid >> 2) * 64;
    int n_base = (wid & 3) * 32;
    int g = lane >> 3, ri = lane & 7;

    uint32_t aoff[4], boff[2];
#pragma unroll
    for (int mf = 0; mf < 4; mf++)
        aoff[mf] = (uint32_t)((m_base + mf * 16 + ri + (g & 1) * 8) * SSTR + (g >> 1) * 8) * 2;
#pragma unroll
    for (int nb = 0; nb < 2; nb++)
        boff[nb] = (uint32_t)((n_base + nb * 16 + ri + (g >> 1) * 8) * SSTR + (g & 1) * 8) * 2;

    float acc[4][4][4];
#pragma unroll
    for (int mf = 0; mf < 4; mf++)
#pragma unroll
        for (int nf = 0; nf < 4; nf++)
#pragma unroll
            for (int q = 0; q < 4; q++) acc[mf][nf][q] = 0.f;

#pragma unroll
    for (int ks = 0; ks < 8; ks++) {
        uint32_t kb = ks * 32;
        uint32_t ah[4][4], al[4][4], bh[2][4], bl[2][4];
#pragma unroll
        for (int mf = 0; mf < 4; mf++) {
            ldm4(ah[mf], sb + EHI_OFF + aoff[mf] + kb);
            ldm4(al[mf], sb + ELO_OFF + aoff[mf] + kb);
        }
#pragma unroll
        for (int nb = 0; nb < 2; nb++) {
            ldm4(bh[nb], sb + WHI_OFF + boff[nb] + kb);
            ldm4(bl[nb], sb + WLO_OFF + boff[nb] + kb);
        }
#pragma unroll
        for (int mf = 0; mf < 4; mf++) {
#pragma unroll
            for (int nf = 0; nf < 4; nf++) {
                const uint32_t* bhp = &bh[nf >> 1][(nf & 1) * 2];
                const uint32_t* blp = &bl[nf >> 1][(nf & 1) * 2];
                mma_bf16(acc[mf][nf], ah[mf], bhp);
                mma_bf16(acc[mf][nf], ah[mf], blp);
                mma_bf16(acc[mf][nf], al[mf], bhp);
            }
        }
    }

    // ---- epilogue: LN fold + store ----
#pragma unroll
    for (int mf = 0; mf < 4; mf++) {
        int r0 = m0 + m_base + mf * 16 + (lane >> 2);
        float mean0 = __ldg(g_mean + r0), rstd0 = __ldg(g_rstd + r0);
        float mean1 = __ldg(g_mean + r0 + 8), rstd1 = __ldg(g_rstd + r0 + 8);
#pragma unroll
        for (int nf = 0; nf < 4; nf++) {
            int col = n_base + nf * 8 + (lane & 3) * 2;
            float2 w1v = *(const float2*)(g_w1 + col);
            float2 c0v = *(const float2*)(g_c0 + col);
            float2 o0, o1;
            o0.x = fmaf(rstd0, acc[mf][nf][0] - mean0 * w1v.x, c0v.x);
            o0.y = fmaf(rstd0, acc[mf][nf][1] - mean0 * w1v.y, c0v.y);
            o1.x = fmaf(rstd1, acc[mf][nf][2] - mean1 * w1v.x, c0v.x);
            o1.y = fmaf(rstd1, acc[mf][nf][3] - mean1 * w1v.y, c0v.y);
            *(float2*)(out + (size_t)r0 * 128 + col) = o0;
            *(float2*)(out + (size_t)(r0 + 8) * 128 + col) = o1;
        }
    }
}

// ---------------- launch ----------------
extern "C" void kernel_launch(void* const* d_in, const int* in_sizes, int n_in,
                              void* d_out, int out_size) {
    const float* X        = (const float*)d_in[0];
    const float* node_h   = (const float*)d_in[1];
    const float* f_node   = (const float*)d_in[2];
    const float* Wpos     = (const float*)d_in[3];
    const float* bpos     = (const float*)d_in[4];
    const float* We       = (const float*)d_in[5];
    const float* ln_scale = (const float*)d_in[6];
    const float* ln_bias  = (const float*)d_in[7];
    const float* Wproj    = (const float*)d_in[8];
    const float* bproj    = (const float*)d_in[9];
    const int*   aatype   = (const int*)d_in[10];
    const int*   resi     = (const int*)d_in[11];
    float* out = (float*)d_out;

    cudaFuncSetAttribute(knn_kernel, cudaFuncAttributeMaxDynamicSharedMemorySize, 3 * L * 4);
    cudaFuncSetAttribute(features_kernel, cudaFuncAttributeMaxDynamicSharedMemorySize, 32768);
    cudaFuncSetAttribute(proj_gemm_kernel, cudaFuncAttributeMaxDynamicSharedMemorySize, GEMM_SMEM);

    prep_small_kernel<<<32, 256>>>(Wproj, ln_scale, ln_bias, bproj, We);
    prep_ab_kernel<<<L / 32, 128>>>(node_h, f_node);
    knn_kernel<<<L / 16, 512, 3 * L * 4>>>(X);
    features_kernel<<<L, 128, 32768>>>(X, Wpos, bpos, aatype, resi);
    proj_gemm_kernel<<<N_TILES, 256, GEMM_SMEM>>>(out);
}

// round 11
// speedup vs baseline: 1.1130x; 1.0111x over previous
#include <cuda_runtime.h>
#include <cuda_bf16.h>
#include <cstdint>
#include <math.h>

#define L 8192
#define K 48
#define SENTK 0xFFFFFFFFFFFFFFFFULL
typedef unsigned long long ull;

#define M_EDGES (L * K)          // 393216
#define N_TILES2 (M_EDGES / 256) // 1536

// ---------------- device scratch (static; allocation-free) ----------------
__device__ __align__(16) float g_A[L * 128];
__device__ __align__(16) float g_B[L * 128];
__device__ __align__(16) ull   g_Wsm2P[16 * 128];
__device__ __align__(16) float g_WAT[128 * 128];
__device__ __align__(16) float g_WfT[128 * 128];
__device__ __align__(16) float g_WhT[128 * 128];
__device__ __align__(16) float g_w1[128];
__device__ __align__(16) float g_c0[128];
__device__ __align__(16) __nv_bfloat16 g_WT_hi[128 * 128];
__device__ __align__(16) __nv_bfloat16 g_WT_lo[128 * 128];
__device__ int   g_knn_idx[L * K];
__device__ float g_knn_d[L * K];
__device__ __align__(16) __nv_bfloat16 g_Ehi[(size_t)M_EDGES * 128];
__device__ __align__(16) __nv_bfloat16 g_Elo[(size_t)M_EDGES * 128];
__device__ float g_mean[M_EDGES];
__device__ float g_rstd[M_EDGES];

// ---------------- helpers ----------------
__device__ __forceinline__ ull fma2(ull a, ull b, ull c) {
    ull d;
    asm("fma.rn.f32x2 %0, %1, %2, %3;" : "=l"(d) : "l"(a), "l"(b), "l"(c));
    return d;
}
__device__ __forceinline__ ull pack2(float lo, float hi) {
    ull d;
    asm("mov.b64 %0, {%1, %2};" : "=l"(d) : "r"(__float_as_uint(lo)), "r"(__float_as_uint(hi)));
    return d;
}
__device__ __forceinline__ float lo2(ull v) { return __uint_as_float((unsigned)v); }
__device__ __forceinline__ float hi2(ull v) { return __uint_as_float((unsigned)(v >> 32)); }

__device__ __forceinline__ uint32_t smem_u32(const void* p) {
    uint32_t a;
    asm("{ .reg .u64 t; cvta.to.shared.u64 t, %1; cvt.u32.u64 %0, t; }" : "=r"(a) : "l"(p));
    return a;
}
__device__ __forceinline__ void ldm4(uint32_t* r, uint32_t addr) {
    asm volatile("ldmatrix.sync.aligned.m8n8.x4.shared.b16 {%0,%1,%2,%3}, [%4];"
                 : "=r"(r[0]), "=r"(r[1]), "=r"(r[2]), "=r"(r[3]) : "r"(addr));
}
__device__ __forceinline__ void mma_bf16(float* c, const uint32_t* a, const uint32_t* b) {
    asm volatile("mma.sync.aligned.m16n8k16.row.col.f32.bf16.bf16.f32 "
                 "{%0,%1,%2,%3}, {%4,%5,%6,%7}, {%8,%9}, {%0,%1,%2,%3};"
                 : "+f"(c[0]), "+f"(c[1]), "+f"(c[2]), "+f"(c[3])
                 : "r"(a[0]), "r"(a[1]), "r"(a[2]), "r"(a[3]), "r"(b[0]), "r"(b[1]));
}

// ---------------- tiny precompute ----------------
__global__ void prep_small_kernel(const float* __restrict__ Wproj,
                                  const float* __restrict__ ln_scale,
                                  const float* __restrict__ ln_bias,
                                  const float* __restrict__ bproj,
                                  const float* __restrict__ We) {
    int gid = blockIdx.x * blockDim.x + threadIdx.x;
    int NT = gridDim.x * blockDim.x;
    for (int n = gid; n < 16384; n += NT) {
        int c = n >> 7, t = n & 127;
        g_WAT[n] = We[t * 416 + 160 + c];
        g_WfT[n] = We[t * 416 + c];
        g_WhT[n] = We[t * 416 + 288 + c];
        int tt = n >> 7, cc = n & 127;
        float w = Wproj[tt * 128 + cc] * ln_scale[cc];
        __nv_bfloat16 h = __float2bfloat16(w);
        float res = w - __bfloat162float(h);
        g_WT_hi[n] = h;
        g_WT_lo[n] = __float2bfloat16(res);
    }
    for (int n = gid; n < 2048; n += NT) {
        int q2 = n >> 7, c = n & 127;
        g_Wsm2P[n] = pack2(We[c * 416 + 128 + 2 * q2], We[c * 416 + 128 + 2 * q2 + 1]);
    }
    if (gid < 128) {
        float s1 = 0.f, s0 = 0.f;
        for (int c = 0; c < 128; c++) {
            float w = Wproj[gid * 128 + c];
            s1 += w * ln_scale[c];
            s0 += w * ln_bias[c];
        }
        g_w1[gid] = s1;
        g_c0[gid] = s0 + bproj[gid];
    }
}

// ---------------- A/B tables ----------------
__global__ void __launch_bounds__(128) prep_ab_kernel(const float* __restrict__ node_h,
                                                      const float* __restrict__ f_node) {
    __shared__ float nh[32 * 128];
    __shared__ float fn[32 * 128];
    int tid = threadIdx.x;
    int i0 = blockIdx.x * 32;
    for (int f = tid; f < 32 * 128; f += 128) {
        nh[f] = node_h[i0 * 128 + f];
        fn[f] = f_node[i0 * 128 + f];
    }
    __syncthreads();
    for (int ch = 0; ch < 4; ch++) {
        float a[8], b[8];
#pragma unroll
        for (int ii = 0; ii < 8; ii++) { a[ii] = 0.f; b[ii] = 0.f; }
#pragma unroll 4
        for (int c = 0; c < 128; c++) {
            float wa = __ldg(g_WAT + c * 128 + tid);
            float wf = __ldg(g_WfT + c * 128 + tid);
            float wh = __ldg(g_WhT + c * 128 + tid);
#pragma unroll
            for (int ii = 0; ii < 8; ii++) {
                int row = ch * 8 + ii;
                float n = nh[row * 128 + c];
                float f = fn[row * 128 + c];
                a[ii] = fmaf(n, wa, a[ii]);
                b[ii] = fmaf(f, wf, fmaf(n, wh, b[ii]));
            }
        }
#pragma unroll
        for (int ii = 0; ii < 8; ii++) {
            g_A[(i0 + ch * 8 + ii) * 128 + tid] = a[ii];
            g_B[(i0 + ch * 8 + ii) * 128 + tid] = b[ii];
        }
    }
}

// ---------------- KNN: redux-based argmin rounds ----------------
__global__ void __launch_bounds__(512) knn_kernel(const float* __restrict__ X) {
    extern __shared__ float sx[];
    int tid = threadIdx.x;
    for (int idx = tid; idx < L; idx += 512) {
        sx[idx]         = X[3 * idx];
        sx[L + idx]     = X[3 * idx + 1];
        sx[2 * L + idx] = X[3 * idx + 2];
    }
    __syncthreads();
    int lane = tid & 31;
    int i = blockIdx.x * 16 + (tid >> 5);
    float xi = sx[i], yi = sx[L + i], zi = sx[2 * L + i];

    ull h[8];
#pragma unroll
    for (int m = 0; m < 8; m++) h[m] = SENTK;

#pragma unroll 4
    for (int s = 0; s < L / 32; s++) {
        int j = lane + (s << 5);
        float dx = xi - sx[j], dy = yi - sx[L + j], dz = zi - sx[2 * L + j];
        float ssq = __fadd_rn(__fadd_rn(__fmul_rn(dx, dx), __fmul_rn(dy, dy)), __fmul_rn(dz, dz));
        unsigned sb = __float_as_uint(ssq);
        unsigned hs = (unsigned)(h[7] >> 32);
        if (sb < hs || (sb == hs && (unsigned)j < (unsigned)h[7])) {
            h[7] = ((ull)sb << 32) | (unsigned)j;
#pragma unroll
            for (int m = 7; m > 0; m--)
                if (h[m] < h[m - 1]) { ull t = h[m]; h[m] = h[m - 1]; h[m - 1] = t; }
        }
    }

    ull mylast = 0ULL;
    for (int r = 0; r < K; r++) {
        if (h[0] == SENTK) {
            for (int s = 0; s < L / 32; s++) {
                int j = lane + (s << 5);
                float dx = xi - sx[j], dy = yi - sx[L + j], dz = zi - sx[2 * L + j];
                float ssq = __fadd_rn(__fadd_rn(__fmul_rn(dx, dx), __fmul_rn(dy, dy)), __fmul_rn(dz, dz));
                ull key = ((ull)__float_as_uint(ssq) << 32) | (unsigned)j;
                if (key > mylast && key < h[7]) {
                    h[7] = key;
#pragma unroll
                    for (int m = 7; m > 0; m--)
                        if (h[m] < h[m - 1]) { ull t = h[m]; h[m] = h[m - 1]; h[m - 1] = t; }
                }
            }
        }
        // warp argmin via 2x REDUX (keys unique; lexicographic (ssq_bits, j))
        unsigned hi = (unsigned)(h[0] >> 32);
        unsigned lo = (unsigned)h[0];
        unsigned hi_min = __reduce_min_sync(0xffffffffu, hi);
        unsigned lo_c = (hi == hi_min) ? lo : 0xffffffffu;
        unsigned lo_min = __reduce_min_sync(0xffffffffu, lo_c);
        ull mn = ((ull)hi_min << 32) | lo_min;
        if (h[0] == mn) {
            mylast = mn;
#pragma unroll
            for (int m = 0; m < 7; m++) h[m] = h[m + 1];
            h[7] = SENTK;
            g_knn_idx[i * K + r] = (int)lo_min;
            float ssq = __uint_as_float(hi_min);
            g_knn_d[i * K + r] = sqrtf(ssq + 1e-6f);
        }
    }
}

// ---------------- features: smem-parallel phase A + phases B/LN ----------------
// float offsets in smem
#define F_SE    0        // 48*132 = 6336
#define F_SML   6336     // 48*32  = 1536
#define F_SA    7872     // 128
#define F_SJ    8000     // 48 (int)
#define F_SD    8048     // 48
#define F_WPOS  8096     // 1056
#define F_BPOS  9152     // 16
#define F_GM    9168     // 48*8 = 384
#define F_P     9552     // 48 (int)
#define F_AA    9600     // 48 (int)
#define F_TOT_B 38592    // 9648 floats

__global__ void __launch_bounds__(128, 4) features_kernel(const float* __restrict__ X,
                                                          const float* __restrict__ Wpos,
                                                          const float* __restrict__ bpos,
                                                          const int* __restrict__ aatype,
                                                          const int* __restrict__ resi) {
    extern __shared__ float sm[];
    float* sE     = sm + F_SE;
    float* sSmall = sm + F_SML;
    float* sA     = sm + F_SA;
    int*   sJ     = (int*)(sm + F_SJ);
    float* sD     = sm + F_SD;
    float* sWpos  = sm + F_WPOS;
    float* sbpos  = sm + F_BPOS;
    float* sGm    = sm + F_GM;
    int*   sP     = (int*)(sm + F_P);
    int*   sAA    = (int*)(sm + F_AA);

    int tid = threadIdx.x;
    int i = blockIdx.x;

    if (tid < 32) ((float4*)sA)[tid] = ((const float4*)(g_A + (size_t)i * 128))[tid];
    if (tid < K) { sJ[tid] = g_knn_idx[i * K + tid]; sD[tid] = g_knn_d[i * K + tid]; }
    for (int n = tid; n < 1056; n += 128) sWpos[n] = __ldg(Wpos + n);
    if (tid >= 64 && tid < 80) sbpos[tid - 64] = __ldg(bpos + tid - 64);
    __syncthreads();

    // Phase A1 (48 threads): transcendentals + lookups -> smem
    if (tid < K) {
        int k = tid;
        int j = sJ[k];
        float d = sD[k];
#pragma unroll
        for (int q = 0; q < 16; q++) {
            float mu = 2.0f + (20.0f / 15.0f) * (float)q;
            float t = (d - mu) * 0.8f;
            sSmall[k * 32 + 16 + q] = expf(-t * t);
        }
        sGm[k * 8 + 0] = d * 0.1f;
        sGm[k * 8 + 1] = 1.0f / (1.0f + d);
        sGm[k * 8 + 2] = expf(-d);
        sGm[k * 8 + 3] = sinf(d);
        sGm[k * 8 + 4] = cosf(d);
        float inv = 1.0f / (d + 1e-6f);
        float xs = X[3 * i], ys = X[3 * i + 1], zs = X[3 * i + 2];
        sGm[k * 8 + 5] = (X[3 * j] - xs) * inv;
        sGm[k * 8 + 6] = (X[3 * j + 1] - ys) * inv;
        sGm[k * 8 + 7] = (X[3 * j + 2] - zs) * inv;
        int off = resi[j] - resi[i];
        sP[k] = min(max(off + 8, 0), 15);
        sAA[k] = aatype[j];
    }
    __syncthreads();

    // Phase A2 (128 threads over 768 (k,r) units): all-smem dot products
#pragma unroll
    for (int it = 0; it < 6; it++) {
        int u = it * 128 + tid;
        int k = u >> 4, r = u & 15;
        const float* wr = sWpos + r * 66;
        float acc = sbpos[r] + wr[sP[k]] + wr[40 + sAA[k]];
        const float* rb = sSmall + k * 32 + 16;
#pragma unroll
        for (int q = 0; q < 16; q++) acc = fmaf(rb[q], wr[16 + q], acc);
        const float* gm = sGm + k * 8;
#pragma unroll
        for (int g = 0; g < 8; g++) acc = fmaf(gm[g], wr[32 + g], acc);
        sSmall[k * 32 + r] = acc;
    }
    __syncthreads();

    // Phase B: coalesced w2; emit fp32 sE + bf16 hi/lo global
    {
        int c = tid;
        ull w2[16];
#pragma unroll
        for (int q2 = 0; q2 < 16; q2++) w2[q2] = __ldg(g_Wsm2P + q2 * 128 + c);
        float a = sA[c];
        size_t ebase = (size_t)i * K * 128;
        for (int k0 = 0; k0 < K; k0 += 4) {
            ull acc[4];
#pragma unroll
            for (int kk = 0; kk < 4; kk++)
                acc[kk] = pack2(a + __ldg(g_B + (size_t)sJ[k0 + kk] * 128 + c), 0.f);
#pragma unroll
            for (int q2 = 0; q2 < 16; q2++) {
#pragma unroll
                for (int kk = 0; kk < 4; kk++) {
                    ull s2 = *(const ull*)(sSmall + (k0 + kk) * 32 + q2 * 2);
                    acc[kk] = fma2(s2, w2[q2], acc[kk]);
                }
            }
#pragma unroll
            for (int kk = 0; kk < 4; kk++) {
                float e = lo2(acc[kk]) + hi2(acc[kk]);
                sE[(k0 + kk) * 132 + c] = e;
                __nv_bfloat16 h = __float2bfloat16(e);
                __nv_bfloat16 l = __float2bfloat16(e - __bfloat162float(h));
                g_Ehi[ebase + (size_t)(k0 + kk) * 128 + c] = h;
                g_Elo[ebase + (size_t)(k0 + kk) * 128 + c] = l;
            }
        }
    }
    __syncthreads();

    // LN stats (fp32)
    {
        int wrp = tid >> 5, lane = tid & 31;
        for (int k = wrp; k < K; k += 4) {
            float s = 0.f, ss = 0.f;
#pragma unroll
            for (int q = 0; q < 4; q++) {
                float v = sE[k * 132 + lane + q * 32];
                s += v;
                ss = fmaf(v, v, ss);
            }
#pragma unroll
            for (int off = 16; off > 0; off >>= 1) {
                s += __shfl_xor_sync(0xffffffffu, s, off);
                ss += __shfl_xor_sync(0xffffffffu, ss, off);
            }
            if (lane == 0) {
                float mean = s * (1.0f / 128.0f);
                float var = ss * (1.0f / 128.0f) - mean * mean;
                g_mean[i * K + k] = mean;
                g_rstd[i * K + k] = rsqrtf(var + 1e-5f);
            }
        }
    }
}

// ---------------- projection GEMM: 256-row M-tile, two 128-row passes ----------------
#define SSTR 136
#define EHI_OFF 0
#define ELO_OFF (256 * SSTR * 2)          // 69632
#define WHI_OFF (2 * 256 * SSTR * 2)      // 139264
#define WLO_OFF (WHI_OFF + 128 * SSTR * 2) // 174080
#define GEMM_SMEM (WLO_OFF + 128 * SSTR * 2) // 208896

__global__ void __launch_bounds__(256, 1) proj_gemm_kernel(float* __restrict__ out) {
    extern __shared__ __align__(16) char gsm[];
    uint32_t sb = smem_u32(gsm);
    int tid = threadIdx.x;
    int wid = tid >> 5, lane = tid & 31;
    int m0 = blockIdx.x * 256;

    // ---- stage W hi/lo ----
#pragma unroll
    for (int it = 0; it < 8; it++) {
        int vec = it * 256 + tid;
        int n = vec >> 4;
        int c8 = (vec & 15) << 3;
        uint32_t so = (uint32_t)n * (SSTR * 2) + c8 * 2;
        *(uint4*)(gsm + WHI_OFF + so) = __ldg((const uint4*)(g_WT_hi + (size_t)n * 128 + c8));
        *(uint4*)(gsm + WLO_OFF + so) = __ldg((const uint4*)(g_WT_lo + (size_t)n * 128 + c8));
    }
    // ---- stage E hi/lo (256 rows) ----
#pragma unroll
    for (int it = 0; it < 16; it++) {
        int vec = it * 256 + tid;
        int r = vec >> 4;
        int c8 = (vec & 15) << 3;
        uint32_t so = (uint32_t)r * (SSTR * 2) + c8 * 2;
        *(uint4*)(gsm + EHI_OFF + so) = __ldg((const uint4*)(g_Ehi + ((size_t)(m0 + r) << 7) + c8));
        *(uint4*)(gsm + ELO_OFF + so) = __ldg((const uint4*)(g_Elo + ((size_t)(m0 + r) << 7) + c8));
    }
    __syncthreads();

    int g = lane >> 3, ri = lane & 7;
    int n_base = (wid & 3) * 32;
    uint32_t boff[2];
#pragma unroll
    for (int nb = 0; nb < 2; nb++)
        boff[nb] = (uint32_t)((n_base + nb * 16 + ri + (g >> 1) * 8) * SSTR + (g & 1) * 8) * 2;

#pragma unroll
    for (int half = 0; half < 2; half++) {
        int m_base = half * 128 + (wid >> 2) * 64;
        uint32_t aoff[4];
#pragma unroll
        for (int mf = 0; mf < 4; mf++)
            aoff[mf] = (uint32_t)((m_base + mf * 16 + ri + (g & 1) * 8) * SSTR + (g >> 1) * 8) * 2;

        float acc[4][4][4];
#pragma unroll
        for (int mf = 0; mf < 4; mf++)
#pragma unroll
            for (int nf = 0; nf < 4; nf++)
#pragma unroll
                for (int q = 0; q < 4; q++) acc[mf][nf][q] = 0.f;

#pragma unroll
        for (int ks = 0; ks < 8; ks++) {
            uint32_t kb = ks * 32;
            uint32_t ah[4][4], al[4][4], bh[2][4], bl[2][4];
#pragma unroll
            for (int mf = 0; mf < 4; mf++) {
                ldm4(ah[mf], sb + EHI_OFF + aoff[mf] + kb);
                ldm4(al[mf], sb + ELO_OFF + aoff[mf] + kb);
            }
#pragma unroll
            for (int nb = 0; nb < 2; nb++) {
                ldm4(bh[nb], sb + WHI_OFF + boff[nb] + kb);
                ldm4(bl[nb], sb + WLO_OFF + boff[nb] + kb);
            }
#pragma unroll
            for (int mf = 0; mf < 4; mf++) {
#pragma unroll
                for (int nf = 0; nf < 4; nf++) {
                    const uint32_t* bhp = &bh[nf >> 1][(nf & 1) * 2];
                    const uint32_t* blp = &bl[nf >> 1][(nf & 1) * 2];
                    mma_bf16(acc[mf][nf], ah[mf], bhp);
                    mma_bf16(acc[mf][nf], ah[mf], blp);
                    mma_bf16(acc[mf][nf], al[mf], bhp);
                }
            }
        }

        // ---- epilogue: LN fold + store ----
#pragma unroll
        for (int mf = 0; mf < 4; mf++) {
            int r0 = m0 + m_base + mf * 16 + (lane >> 2);
            float mean0 = __ldg(g_mean + r0), rstd0 = __ldg(g_rstd + r0);
            float mean1 = __ldg(g_mean + r0 + 8), rstd1 = __ldg(g_rstd + r0 + 8);
#pragma unroll
            for (int nf = 0; nf < 4; nf++) {
                int col = n_base + nf * 8 + (lane & 3) * 2;
                float2 w1v = *(const float2*)(g_w1 + col);
                float2 c0v = *(const float2*)(g_c0 + col);
                float2 o0, o1;
                o0.x = fmaf(rstd0, acc[mf][nf][0] - mean0 * w1v.x, c0v.x);
                o0.y = fmaf(rstd0, acc[mf][nf][1] - mean0 * w1v.y, c0v.y);
                o1.x = fmaf(rstd1, acc[mf][nf][2] - mean1 * w1v.x, c0v.x);
                o1.y = fmaf(rstd1, acc[mf][nf][3] - mean1 * w1v.y, c0v.y);
                *(float2*)(out + (size_t)r0 * 128 + col) = o0;
                *(float2*)(out + (size_t)(r0 + 8) * 128 + col) = o1;
            }
        }
    }
}

// ---------------- launch ----------------
extern "C" void kernel_launch(void* const* d_in, const int* in_sizes, int n_in,
                              void* d_out, int out_size) {
    const float* X        = (const float*)d_in[0];
    const float* node_h   = (const float*)d_in[1];
    const float* f_node   = (const float*)d_in[2];
    const float* Wpos     = (const float*)d_in[3];
    const float* bpos     = (const float*)d_in[4];
    const float* We       = (const float*)d_in[5];
    const float* ln_scale = (const float*)d_in[6];
    const float* ln_bias  = (const float*)d_in[7];
    const float* Wproj    = (const float*)d_in[8];
    const float* bproj    = (const float*)d_in[9];
    const int*   aatype   = (const int*)d_in[10];
    const int*   resi     = (const int*)d_in[11];
    float* out = (float*)d_out;

    cudaFuncSetAttribute(knn_kernel, cudaFuncAttributeMaxDynamicSharedMemorySize, 3 * L * 4);
    cudaFuncSetAttribute(features_kernel, cudaFuncAttributeMaxDynamicSharedMemorySize, F_TOT_B);
    cudaFuncSetAttribute(proj_gemm_kernel, cudaFuncAttributeMaxDynamicSharedMemorySize, GEMM_SMEM);

    prep_small_kernel<<<32, 256>>>(Wproj, ln_scale, ln_bias, bproj, We);
    prep_ab_kernel<<<L / 32, 128>>>(node_h, f_node);
    knn_kernel<<<L / 16, 512, 3 * L * 4>>>(X);
    features_kernel<<<L, 128, F_TOT_B>>>(X, Wpos, bpos, aatype, resi);
    proj_gemm_kernel<<<N_TILES2, 256, GEMM_SMEM>>>(out);
}